// round 10
// baseline (speedup 1.0000x reference)
#include <cuda_runtime.h>
#include <cstdint>

// MaxUnpooling2D: updates [16,64,64,256] f32, mask [16,64,64,256] i32
// (flattened per-batch output index), out [16,128,128,256] f32.
//
// Each pooled element scatters into its OWN 2x2 window at the SAME channel
// => output cells are covered exactly once. Fused zero-fill + scatter.
//
// R9: read/write PHASE SEPARATION. R6 far-split structure (2 float4 groups
// per thread, all warp accesses dense 512B bursts, payload in registers)
// + one __syncthreads() between the load phase (4 LDG.128) and the store
// phase (8 STG.128). CTA-aligned phases give the DRAM scheduler longer
// same-direction bursts, attacking the read/write turnaround that R5-R8
// evidence suggests pins us at ~72% DRAM.
// R10: resubmit (round 9 bench was an infra container failure). Barrier is
// safe: half = 8192*256 exactly, so no thread takes the early-return path.

#define C_  256
#define WO_ 128
#define HOWOC_ (128 * 128 * 256)   // per-batch output elements

__device__ __forceinline__ void scatter_one(
    const int4& m, const float4& u, int e, float* __restrict__ out)
{
    // Decode float4-group index e: c4 [0,6), w [6,12), h [12,18), b [18,22).
    int c4 = e & 63;
    int w  = (e >> 6)  & 63;
    int h  = (e >> 12) & 63;
    int b  = e >> 18;

    int base = h * (2 * WO_ * C_) + w * (2 * C_) + (c4 << 2);
    float* ob = out + (size_t)b * HOWOC_ + base;

    const int offs[4] = {0, C_, WO_ * C_, WO_ * C_ + C_};
#pragma unroll
    for (int k = 0; k < 4; k++) {
        int a = base + offs[k];
        float4 v;
        v.x = (m.x == a + 0) ? u.x : 0.0f;
        v.y = (m.y == a + 1) ? u.y : 0.0f;
        v.z = (m.z == a + 2) ? u.z : 0.0f;
        v.w = (m.w == a + 3) ? u.w : 0.0f;
        *reinterpret_cast<float4*>(ob + offs[k]) = v;
    }
}

__global__ void __launch_bounds__(256) max_unpool_kernel(
    const float4* __restrict__ upd,
    const int4*   __restrict__ msk,
    float*        __restrict__ out,
    int half)
{
    int t = blockIdx.x * blockDim.x + threadIdx.x;
    if (t >= half) return;
    int t2 = t + half;

    // ---- load phase: 4 independent fully-coalesced LDG.128 ----
    int4   m0 = msk[t];
    int4   m1 = msk[t2];
    float4 u0 = upd[t];
    float4 u1 = upd[t2];

    // Align phases CTA-wide: all reads issued before any write.
    __syncthreads();

    // ---- store phase: 8 fully-coalesced STG.128 ----
    scatter_one(m0, u0, t,  out);
    scatter_one(m1, u1, t2, out);
}

extern "C" void kernel_launch(void* const* d_in, const int* in_sizes, int n_in,
                              void* d_out, int out_size)
{
    const float4* upd = (const float4*)d_in[0];
    const int4*   msk = (const int4*)d_in[1];
    float*        out = (float*)d_out;

    int n    = in_sizes[0];   // 16*64*64*256 = 16,777,216
    int n4   = n >> 2;        // 4,194,304 float4 groups
    int half = n4 >> 1;       // 2,097,152 threads

    int threads = 256;
    int blocks  = (half + threads - 1) / threads;   // 8192
    max_unpool_kernel<<<blocks, threads>>>(upd, msk, out, half);
}

// round 11
// speedup vs baseline: 1.0329x; 1.0329x over previous
#include <cuda_runtime.h>
#include <cstdint>

// MaxUnpooling2D: updates [16,64,64,256] f32, mask [16,64,64,256] i32
// (flattened per-batch output index), out [16,128,128,256] f32.
//
// Each pooled element scatters into its OWN 2x2 window at the SAME channel
// => output cells are covered exactly once by the union of all
// (thread, window-cell) stores. Fused zero-fill + scatter: each thread owns
// 4 channels of one pooled element and writes all 4 window cells as float4
// (selected value or zero). Fully dense, fully coalesced.
//
// R5-R10 established: MLP, cache policy, 256-bit width, and r/w phasing are
// all neutral; the kernel sits at the HBM mixed-stream ceiling (~72% DRAM,
// logical bytes at the 403MB floor). R11: best structure (R1/R7) with
// block=512 — the last untouched knob (fewer CTAs, longer per-CTA runs).

#define C_  256
#define WO_ 128
#define HOWOC_ (128 * 128 * 256)   // per-batch output elements

__global__ void __launch_bounds__(512) max_unpool_kernel(
    const float4* __restrict__ upd,
    const int4*   __restrict__ msk,
    float*        __restrict__ out,
    int n4)
{
    int t = blockIdx.x * blockDim.x + threadIdx.x;
    if (t >= n4) return;

    int4   m = __ldcs(msk + t);
    float4 u = __ldcs(upd + t);

    // Decode coords from linear float4 index. C/4 = 64, W = 64, H = 64.
    int c4 = t & 63;
    int w  = (t >> 6) & 63;
    int h  = (t >> 12) & 63;
    int b  = t >> 18;

    // Per-batch flattened base address of window cell (0,0), channel 4*c4.
    int base = h * (2 * WO_ * C_) + w * (2 * C_) + (c4 << 2);

    float* ob = out + (size_t)b * HOWOC_ + base;

    // Window-cell offsets: (di*Wo + dj)*C for (di,dj) in {0,1}^2.
    const int offs[4] = {0, C_, WO_ * C_, WO_ * C_ + C_};

#pragma unroll
    for (int k = 0; k < 4; k++) {
        int a = base + offs[k];
        float4 v;
        v.x = (m.x == a + 0) ? u.x : 0.0f;
        v.y = (m.y == a + 1) ? u.y : 0.0f;
        v.z = (m.z == a + 2) ? u.z : 0.0f;
        v.w = (m.w == a + 3) ? u.w : 0.0f;
        __stcs(reinterpret_cast<float4*>(ob + offs[k]), v);
    }
}

extern "C" void kernel_launch(void* const* d_in, const int* in_sizes, int n_in,
                              void* d_out, int out_size)
{
    const float4* upd = (const float4*)d_in[0];
    const int4*   msk = (const int4*)d_in[1];
    float*        out = (float*)d_out;

    int n  = in_sizes[0];       // 16*64*64*256 = 16,777,216
    int n4 = n >> 2;            // 4,194,304 float4 work items

    int threads = 512;
    int blocks  = (n4 + threads - 1) / threads;   // 8192
    max_unpool_kernel<<<blocks, threads>>>(upd, msk, out, n4);
}